// round 1
// baseline (speedup 1.0000x reference)
#include <cuda_runtime.h>
#include <math.h>

// Fixed problem shapes (from reference setup_inputs)
#define B_   4
#define N_   10
#define K_   5
#define Q_   512
#define D_   1536

#define QS_      8                 // Q split factor
#define QCHUNK_  (Q_ / QS_)        // 64 queries per block
#define DB_      12                // D split factor
#define DCHUNK_  (D_ / DB_)        // 128 dims per block (= blockDim)

// Scratch (allocation-free: __device__ globals)
__device__ float g_qsum[B_ * QS_ * D_];   // partial column sums of query
__device__ float g_ss  [B_ * QS_ * DB_];  // partial sum-of-squares per block
__device__ float g_qbar[B_ * D_];         // per-batch mean query vector

// ---------------------------------------------------------------------------
// Kernel 1: column partial sums + sum-of-squares of query.
// grid = (B, DB, QS), block = 128. Fully coalesced (tid -> consecutive d).
// ---------------------------------------------------------------------------
__global__ void qstats_kernel(const float* __restrict__ query) {
    const int b    = blockIdx.x;
    const int dblk = blockIdx.y;
    const int qs   = blockIdx.z;
    const int d    = dblk * DCHUNK_ + threadIdx.x;

    const float* qp = query + (size_t)b * Q_ * D_ + (size_t)qs * QCHUNK_ * D_ + d;

    float s = 0.f, ss = 0.f;
    #pragma unroll 8
    for (int i = 0; i < QCHUNK_; i++) {
        float v = qp[(size_t)i * D_];
        s  += v;
        ss += v * v;
    }
    g_qsum[(b * QS_ + qs) * D_ + d] = s;

    // block-reduce ss
    __shared__ float red[DCHUNK_];
    red[threadIdx.x] = ss;
    __syncthreads();
    for (int off = DCHUNK_ / 2; off > 0; off >>= 1) {
        if (threadIdx.x < off) red[threadIdx.x] += red[threadIdx.x + off];
        __syncthreads();
    }
    if (threadIdx.x == 0)
        g_ss[b * (QS_ * DB_) + qs * DB_ + dblk] = red[0];
}

// ---------------------------------------------------------------------------
// Kernel 2: reduce Q-partials -> q_bar (mean query vector per batch)
// ---------------------------------------------------------------------------
__global__ void qbar_kernel() {
    int idx = blockIdx.x * blockDim.x + threadIdx.x;   // over B*D
    if (idx >= B_ * D_) return;
    int b = idx / D_;
    int d = idx - b * D_;
    float s = 0.f;
    #pragma unroll
    for (int qs = 0; qs < QS_; qs++)
        s += g_qsum[(b * QS_ + qs) * D_ + d];
    g_qbar[idx] = s * (1.0f / Q_);
}

// ---------------------------------------------------------------------------
// Kernel 3: per (b, n) block: t_k = -(||S_k||^2 - 2 S_k.qbar + c_b),
// w = softmax_k(tanh(t)), write qgw, then agg[b,n,:] = sum_k w_k * S_k.
// grid = B*N = 40 blocks, 256 threads.
// ---------------------------------------------------------------------------
__global__ void agg_kernel(const float* __restrict__ support,
                           float* __restrict__ out) {
    const int bn = blockIdx.x;
    const int b  = bn / N_;
    const int tid = threadIdx.x;

    __shared__ float sh[256];
    __shared__ float s_dot[K_], s_nrm[K_], s_c, s_w[K_];

    // c_b = mean_q ||q||^2  (sum the 96 partials)
    float cv = 0.f;
    for (int i = tid; i < QS_ * DB_; i += 256)
        cv += g_ss[b * (QS_ * DB_) + i];
    sh[tid] = cv; __syncthreads();
    for (int off = 128; off > 0; off >>= 1) {
        if (tid < off) sh[tid] += sh[tid + off];
        __syncthreads();
    }
    if (tid == 0) s_c = sh[0] * (1.0f / Q_);
    __syncthreads();

    const float* sup = support + (size_t)bn * K_ * D_;

    float dot[K_], nrm[K_];
    #pragma unroll
    for (int k = 0; k < K_; k++) { dot[k] = 0.f; nrm[k] = 0.f; }

    for (int d = tid; d < D_; d += 256) {
        float qb = g_qbar[b * D_ + d];
        #pragma unroll
        for (int k = 0; k < K_; k++) {
            float sv = sup[k * D_ + d];
            dot[k] += sv * qb;
            nrm[k] += sv * sv;
        }
    }

    // reduce the 10 scalars through shared memory
    #pragma unroll
    for (int k = 0; k < K_; k++) {
        sh[tid] = dot[k]; __syncthreads();
        for (int off = 128; off > 0; off >>= 1) {
            if (tid < off) sh[tid] += sh[tid + off];
            __syncthreads();
        }
        if (tid == 0) s_dot[k] = sh[0];
        __syncthreads();

        sh[tid] = nrm[k]; __syncthreads();
        for (int off = 128; off > 0; off >>= 1) {
            if (tid < off) sh[tid] += sh[tid + off];
            __syncthreads();
        }
        if (tid == 0) s_nrm[k] = sh[0];
        __syncthreads();
    }

    if (tid == 0) {
        float t[K_];
        float m = -1e30f;
        #pragma unroll
        for (int k = 0; k < K_; k++) {
            t[k] = tanhf(-(s_nrm[k] - 2.0f * s_dot[k] + s_c));
            m = fmaxf(m, t[k]);
        }
        float Z = 0.f;
        #pragma unroll
        for (int k = 0; k < K_; k++) { t[k] = expf(t[k] - m); Z += t[k]; }
        float invZ = 1.0f / Z;
        #pragma unroll
        for (int k = 0; k < K_; k++) {
            s_w[k] = t[k] * invZ;
            // qgw output: after agg block (B*N*D floats)
            out[(size_t)B_ * N_ * D_ + bn * K_ + k] = s_w[k];
        }
    }
    __syncthreads();

    float w[K_];
    #pragma unroll
    for (int k = 0; k < K_; k++) w[k] = s_w[k];

    float* outp = out + (size_t)bn * D_;
    for (int d = tid; d < D_; d += 256) {
        float acc = 0.f;
        #pragma unroll
        for (int k = 0; k < K_; k++) acc += w[k] * sup[k * D_ + d];
        outp[d] = acc;
    }
}

extern "C" void kernel_launch(void* const* d_in, const int* in_sizes, int n_in,
                              void* d_out, int out_size) {
    const float* support = (const float*)d_in[0];
    const float* query   = (const float*)d_in[1];
    float* out = (float*)d_out;

    dim3 g1(B_, DB_, QS_);
    qstats_kernel<<<g1, DCHUNK_>>>(query);
    qbar_kernel<<<(B_ * D_ + 255) / 256, 256>>>();
    agg_kernel<<<B_ * N_, 256>>>(support, out);
}

// round 2
// speedup vs baseline: 1.1555x; 1.1555x over previous
#include <cuda_runtime.h>
#include <math.h>

// Fixed problem shapes
#define B_   4
#define N_   10
#define K_   5
#define Q_   512
#define D_   1536
#define D4_  (D_ / 4)      // 384 float4 per row

#define QS_  32            // Q split factor
#define QC_  (Q_ / QS_)    // 16 queries per block
#define DBL_ 3             // D split: 3 blocks of 128 float4 (512 floats)

// Scratch (allocation-free: __device__ globals)
__device__ float4 g_qsum4[B_ * QS_ * D4_];   // partial column sums of query
__device__ float  g_ss  [B_ * QS_ * DBL_];   // partial sum-of-squares

// ---------------------------------------------------------------------------
// Kernel 1: vectorized column partial sums + sum-of-squares of query.
// grid = (B, DBL, QS), block = 128. float4 loads, fully unrolled (16 LDG.128
// in flight per thread) to saturate HBM.
// ---------------------------------------------------------------------------
__global__ void qstats_kernel(const float4* __restrict__ q4) {
    const int b    = blockIdx.x;
    const int dblk = blockIdx.y;
    const int qs   = blockIdx.z;
    const int d4   = dblk * 128 + threadIdx.x;     // 0..383

    const float4* qp = q4 + ((size_t)b * Q_ + (size_t)qs * QC_) * D4_ + d4;

    float4 s = make_float4(0.f, 0.f, 0.f, 0.f);
    float ss = 0.f;
    #pragma unroll
    for (int i = 0; i < QC_; i++) {
        float4 v = qp[(size_t)i * D4_];
        s.x += v.x; s.y += v.y; s.z += v.z; s.w += v.w;
        ss += v.x * v.x + v.y * v.y + v.z * v.z + v.w * v.w;
    }
    g_qsum4[((size_t)(b * QS_ + qs)) * D4_ + d4] = s;

    // warp-shuffle reduce ss, then cross-warp via shared (4 warps)
    #pragma unroll
    for (int off = 16; off > 0; off >>= 1)
        ss += __shfl_down_sync(0xffffffffu, ss, off);

    __shared__ float wred[4];
    if ((threadIdx.x & 31) == 0) wred[threadIdx.x >> 5] = ss;
    __syncthreads();
    if (threadIdx.x == 0)
        g_ss[(b * QS_ + qs) * DBL_ + dblk] = wred[0] + wred[1] + wred[2] + wred[3];
}

// ---------------------------------------------------------------------------
// Kernel 2 (fused qbar + agg): per (b, n) block.
//   qbar  = mean_q query  (reduced from L2-resident partials, into shared)
//   c_b   = mean_q ||q||^2
//   t_k   = tanh(-(||S_k||^2 - 2 S_k.qbar + c_b)),  w = softmax_k(t)
//   out: agg[b,n,:] = sum_k w_k S_k ;  qgw appended after agg block.
// grid = B*N = 40 blocks, 256 threads.
// ---------------------------------------------------------------------------
__global__ void agg_kernel(const float4* __restrict__ sup4,
                           float* __restrict__ out) {
    const int bn   = blockIdx.x;
    const int b    = bn / N_;
    const int tid  = threadIdx.x;
    const int lane = tid & 31;
    const int wid  = tid >> 5;

    __shared__ float4 shq[D4_];          // qbar as float4 (6 KB)
    __shared__ float  wred[8];           // cross-warp scratch (c_b)
    __shared__ float  sred[2 * K_ * 8];  // dot/nrm per-warp partials
    __shared__ float  s_w[K_];

    // ---- qbar into shared (partials are L2-resident) ----
    const float4* qsum = g_qsum4 + (size_t)b * QS_ * D4_;
    for (int d4 = tid; d4 < D4_; d4 += 256) {
        float4 acc = make_float4(0.f, 0.f, 0.f, 0.f);
        #pragma unroll
        for (int qs = 0; qs < QS_; qs++) {
            float4 v = qsum[(size_t)qs * D4_ + d4];
            acc.x += v.x; acc.y += v.y; acc.z += v.z; acc.w += v.w;
        }
        const float inv = 1.0f / Q_;
        acc.x *= inv; acc.y *= inv; acc.z *= inv; acc.w *= inv;
        shq[d4] = acc;
    }

    // ---- c_b = mean_q ||q||^2 ----
    float cv = 0.f;
    for (int i = tid; i < QS_ * DBL_; i += 256)
        cv += g_ss[b * (QS_ * DBL_) + i];
    #pragma unroll
    for (int off = 16; off > 0; off >>= 1)
        cv += __shfl_down_sync(0xffffffffu, cv, off);
    if (lane == 0) wred[wid] = cv;
    __syncthreads();   // covers shq + wred

    float c_b = 0.f;
    #pragma unroll
    for (int w = 0; w < 8; w++) c_b += wred[w];
    c_b *= (1.0f / Q_);

    // ---- dot_k = S_k . qbar , nrm_k = ||S_k||^2 ----
    const float4* sp = sup4 + (size_t)bn * K_ * D4_;
    float dot[K_], nrm[K_];
    #pragma unroll
    for (int k = 0; k < K_; k++) { dot[k] = 0.f; nrm[k] = 0.f; }

    for (int d4 = tid; d4 < D4_; d4 += 256) {
        float4 qb = shq[d4];
        #pragma unroll
        for (int k = 0; k < K_; k++) {
            float4 sv = sp[(size_t)k * D4_ + d4];
            dot[k] += sv.x * qb.x + sv.y * qb.y + sv.z * qb.z + sv.w * qb.w;
            nrm[k] += sv.x * sv.x + sv.y * sv.y + sv.z * sv.z + sv.w * sv.w;
        }
    }

    // warp-shuffle reduce all 10 scalars, one cross-warp pass
    #pragma unroll
    for (int k = 0; k < K_; k++) {
        float dk = dot[k], nk = nrm[k];
        #pragma unroll
        for (int off = 16; off > 0; off >>= 1) {
            dk += __shfl_down_sync(0xffffffffu, dk, off);
            nk += __shfl_down_sync(0xffffffffu, nk, off);
        }
        if (lane == 0) {
            sred[k * 8 + wid]            = dk;
            sred[(K_ + k) * 8 + wid]     = nk;
        }
    }
    __syncthreads();

    if (tid == 0) {
        float t[K_];
        float m = -1e30f;
        #pragma unroll
        for (int k = 0; k < K_; k++) {
            float dk = 0.f, nk = 0.f;
            #pragma unroll
            for (int w = 0; w < 8; w++) {
                dk += sred[k * 8 + w];
                nk += sred[(K_ + k) * 8 + w];
            }
            t[k] = tanhf(-(nk - 2.0f * dk + c_b));
            m = fmaxf(m, t[k]);
        }
        float Z = 0.f;
        #pragma unroll
        for (int k = 0; k < K_; k++) { t[k] = __expf(t[k] - m); Z += t[k]; }
        float invZ = 1.0f / Z;
        #pragma unroll
        for (int k = 0; k < K_; k++) {
            s_w[k] = t[k] * invZ;
            out[(size_t)B_ * N_ * D_ + bn * K_ + k] = t[k] * invZ;
        }
    }
    __syncthreads();

    float w[K_];
    #pragma unroll
    for (int k = 0; k < K_; k++) w[k] = s_w[k];

    float4* outp = (float4*)(out + (size_t)bn * D_);
    for (int d4 = tid; d4 < D4_; d4 += 256) {
        float4 acc = make_float4(0.f, 0.f, 0.f, 0.f);
        #pragma unroll
        for (int k = 0; k < K_; k++) {
            float4 sv = sp[(size_t)k * D4_ + d4];
            acc.x += w[k] * sv.x; acc.y += w[k] * sv.y;
            acc.z += w[k] * sv.z; acc.w += w[k] * sv.w;
        }
        outp[d4] = acc;
    }
}

extern "C" void kernel_launch(void* const* d_in, const int* in_sizes, int n_in,
                              void* d_out, int out_size) {
    const float4* support = (const float4*)d_in[0];
    const float4* query   = (const float4*)d_in[1];
    float* out = (float*)d_out;

    dim3 g1(B_, DBL_, QS_);
    qstats_kernel<<<g1, 128>>>(query);
    agg_kernel<<<B_ * N_, 256>>>(support, out);
}

// round 3
// speedup vs baseline: 1.5970x; 1.3821x over previous
#include <cuda_runtime.h>
#include <math.h>

// Fixed problem shapes
#define B_   4
#define N_   10
#define K_   5
#define Q_   512
#define D_   1536
#define D4_  384            // D/4 float4 per row

#define QS_  32             // Q split per batch
#define QC_  (Q_ / QS_)     // 16 rows per block
#define NBLK_ (B_ * QS_)    // 128 blocks (<=148 SMs -> single co-resident wave)
#define NT_   384           // one thread per d4 column
#define NW_   (NT_ / 32)    // 12 warps

// Scratch (allocation-free: __device__ globals, zero-init at module load)
__device__ float4   g_qsum4[B_ * QS_ * D4_];  // per-(b,qs) column partial sums
__device__ float    g_ss[B_ * QS_];           // per-(b,qs) sum-of-squares
__device__ unsigned g_cnt1;                   // spin barrier counter
__device__ unsigned g_cnt2;                   // arrive-only reset counter

__global__ void __launch_bounds__(NT_, 1)
fused_kernel(const float4* __restrict__ q4,
             const float4* __restrict__ sup4,
             float* __restrict__ out) {
    const int tid  = threadIdx.x;          // = d4 column, 0..383
    const int lane = tid & 31;
    const int wid  = tid >> 5;
    const int bid  = blockIdx.x;

    __shared__ float s_wred[NW_];
    __shared__ float s_red[2 * K_ * NW_];
    __shared__ float s_c;
    __shared__ float s_w[K_];

    // ======================= Phase 1: query stats =======================
    {
        const int b  = bid >> 5;
        const int qs = bid & 31;
        const float4* qp = q4 + ((size_t)(b * Q_ + qs * QC_)) * D4_ + tid;

        float4 s = make_float4(0.f, 0.f, 0.f, 0.f);
        float ss = 0.f;
        #pragma unroll
        for (int i = 0; i < QC_; i++) {
            float4 v = qp[(size_t)i * D4_];
            s.x += v.x; s.y += v.y; s.z += v.z; s.w += v.w;
            ss += v.x * v.x + v.y * v.y + v.z * v.z + v.w * v.w;
        }
        g_qsum4[(size_t)bid * D4_ + tid] = s;

        #pragma unroll
        for (int off = 16; off > 0; off >>= 1)
            ss += __shfl_down_sync(0xffffffffu, ss, off);
        if (lane == 0) s_wred[wid] = ss;
        __syncthreads();
        if (tid == 0) {
            float t = 0.f;
            #pragma unroll
            for (int w = 0; w < NW_; w++) t += s_wred[w];
            g_ss[bid] = t;
        }
    }

    // ======================= Grid barrier =======================
    __syncthreads();
    if (tid == 0) {
        __threadfence();                       // publish g_qsum4 / g_ss
        atomicAdd(&g_cnt1, 1u);
        while (*(volatile unsigned*)&g_cnt1 < (unsigned)NBLK_) { }
    }
    __syncthreads();

    // ======================= Phase 2: weights + aggregation =======================
    if (bid < B_ * N_) {
        const int bn = bid;
        const int bb = bn / N_;

        // qbar for this thread's d4 column (stays in registers)
        const float4* qsum = g_qsum4 + (size_t)bb * QS_ * D4_ + tid;
        float4 qb = make_float4(0.f, 0.f, 0.f, 0.f);
        #pragma unroll
        for (int qs = 0; qs < QS_; qs++) {
            float4 v = qsum[(size_t)qs * D4_];
            qb.x += v.x; qb.y += v.y; qb.z += v.z; qb.w += v.w;
        }
        const float invQ = 1.0f / Q_;
        qb.x *= invQ; qb.y *= invQ; qb.z *= invQ; qb.w *= invQ;

        // c_b = mean_q ||q||^2  (warp 0 only)
        if (wid == 0) {
            float cv = g_ss[bb * QS_ + lane];
            #pragma unroll
            for (int off = 16; off > 0; off >>= 1)
                cv += __shfl_down_sync(0xffffffffu, cv, off);
            if (lane == 0) s_c = cv * invQ;
        }

        // support tile: load once, reuse for dot/nrm and for output
        const float4* sp = sup4 + (size_t)bn * K_ * D4_ + tid;
        float4 sv[K_];
        float dot[K_], nrm[K_];
        #pragma unroll
        for (int k = 0; k < K_; k++) {
            sv[k] = sp[(size_t)k * D4_];
            dot[k] = sv[k].x * qb.x + sv[k].y * qb.y + sv[k].z * qb.z + sv[k].w * qb.w;
            nrm[k] = sv[k].x * sv[k].x + sv[k].y * sv[k].y + sv[k].z * sv[k].z + sv[k].w * sv[k].w;
        }

        #pragma unroll
        for (int k = 0; k < K_; k++) {
            float dk = dot[k], nk = nrm[k];
            #pragma unroll
            for (int off = 16; off > 0; off >>= 1) {
                dk += __shfl_down_sync(0xffffffffu, dk, off);
                nk += __shfl_down_sync(0xffffffffu, nk, off);
            }
            if (lane == 0) {
                s_red[k * NW_ + wid]        = dk;
                s_red[(K_ + k) * NW_ + wid] = nk;
            }
        }
        __syncthreads();

        if (tid == 0) {
            float t[K_];
            float m = -1e30f;
            #pragma unroll
            for (int k = 0; k < K_; k++) {
                float dk = 0.f, nk = 0.f;
                #pragma unroll
                for (int w = 0; w < NW_; w++) {
                    dk += s_red[k * NW_ + w];
                    nk += s_red[(K_ + k) * NW_ + w];
                }
                t[k] = tanhf(-(nk - 2.0f * dk + s_c));
                m = fmaxf(m, t[k]);
            }
            float Z = 0.f;
            #pragma unroll
            for (int k = 0; k < K_; k++) { t[k] = __expf(t[k] - m); Z += t[k]; }
            float invZ = 1.0f / Z;
            #pragma unroll
            for (int k = 0; k < K_; k++) {
                float wk = t[k] * invZ;
                s_w[k] = wk;
                out[(size_t)B_ * N_ * D_ + bn * K_ + k] = wk;   // qgw
            }
        }
        __syncthreads();

        float4 acc = make_float4(0.f, 0.f, 0.f, 0.f);
        #pragma unroll
        for (int k = 0; k < K_; k++) {
            float wk = s_w[k];
            acc.x += wk * sv[k].x; acc.y += wk * sv[k].y;
            acc.z += wk * sv[k].z; acc.w += wk * sv[k].w;
        }
        ((float4*)out)[(size_t)bn * D4_ + tid] = acc;           // agg
    }

    // ======== arrive-only reset barrier (prepares counters for next replay) ========
    if (tid == 0) {
        __threadfence();
        unsigned old = atomicAdd(&g_cnt2, 1u);
        if (old == (unsigned)(NBLK_ - 1)) {
            // Last block: everyone has passed the spin barrier (cnt2 arrival
            // strictly follows cnt1 pass). Reset both for the next graph replay.
            atomicExch(&g_cnt1, 0u);
            atomicExch(&g_cnt2, 0u);
            __threadfence();
        }
    }
}

extern "C" void kernel_launch(void* const* d_in, const int* in_sizes, int n_in,
                              void* d_out, int out_size) {
    const float4* support = (const float4*)d_in[0];
    const float4* query   = (const float4*)d_in[1];
    float* out = (float*)d_out;

    fused_kernel<<<NBLK_, NT_>>>(query, support, out);
}